// round 16
// baseline (speedup 1.0000x reference)
#include <cuda_runtime.h>
#include <cuda_bf16.h>
#include <cuda_fp16.h>
#include <cstdint>

// Problem dims
#define S_ 512
#define B_ 128
#define E_ 100
#define H_ 256
#define T_ 9
#define G_ 1024   // 4*H
#define V_ 6000
#define VPAD 6016

// ---------------- scratch (device globals; no allocations) ----------------
__device__ float g_tab[2][VPAD * G_];            // vocab projection table (+bias)
__device__ __half g_h2[2][S_][2][B_][H_];        // h 2-plane fp16 split (MMA B operand)
__device__ float g_hT[2][S_ * H_ * B_];          // fp32 h transposed [s][u][b] (for MLP)
__device__ float g_em[B_ * S_ * T_];             // emissions [b][s][t]
__device__ unsigned g_flagx[2][4][16][32];       // flags [dir][btile][utile], own 128B line

__device__ __forceinline__ float fsig(float x) {
    return __fdividef(1.f, 1.f + __expf(-x));
}
__device__ __forceinline__ float ftanh(float x) {
    return __fdividef(2.f, 1.f + __expf(-2.f * x)) - 1.f;
}

__device__ __forceinline__ uint32_t smem_u32(const void* p) {
    uint32_t a;
    asm("{ .reg .u64 t; cvta.to.shared.u64 t, %1; cvt.u32.u64 %0, t; }"
        : "=r"(a) : "l"(p));
    return a;
}

// per-half named barrier (256 threads each; ids 1 and 2)
#define HALF_BAR(hid) \
    asm volatile("bar.sync %0, 256;" :: "r"((hid) + 1) : "memory")

#define LDMX4(r, addr) \
    asm volatile("ldmatrix.sync.aligned.m8n8.x4.shared.b16 {%0,%1,%2,%3}, [%4];" \
        : "=r"((r)[0]), "=r"((r)[1]), "=r"((r)[2]), "=r"((r)[3]) : "r"(addr))

__device__ __forceinline__ void mma16816h(float* d, const uint32_t* a, const uint32_t* b) {
    asm volatile(
        "mma.sync.aligned.m16n8k16.row.col.f32.f16.f16.f32 "
        "{%0,%1,%2,%3}, {%4,%5,%6,%7}, {%8,%9}, {%0,%1,%2,%3};"
        : "+f"(d[0]), "+f"(d[1]), "+f"(d[2]), "+f"(d[3])
        : "r"(a[0]), "r"(a[1]), "r"(a[2]), "r"(a[3]), "r"(b[0]), "r"(b[1]));
}

__global__ void reset_kernel() {
    int i = blockIdx.x * blockDim.x + threadIdx.x;
    if (i < 2 * 4 * 16 * 32) ((unsigned*)g_flagx)[i] = 0u;
}

// ---------------- Kernel A: VOCAB projection (per-direction launch) ------
__global__ void vocab_kernel(const float* __restrict__ emb,
                             const float* __restrict__ W,
                             const float* __restrict__ bias,
                             int dir) {
    extern __shared__ float sm[];
    float* Xsm = sm;          // [100][36]
    float* Wsm = sm + 3600;   // [100][132]

    int tt = blockIdx.x;
    int g0 = blockIdx.y * 128;

    for (int idx = threadIdx.x; idx < 32 * E_; idx += 256) {
        int j = idx / E_, k = idx - j * E_;
        int v = tt * 32 + j;
        int row = (v < V_) ? v : 0;
        Xsm[k * 36 + j] = emb[row * E_ + k];
    }
    for (int idx = threadIdx.x; idx < 128 * E_; idx += 256) {
        int r = idx / E_, k = idx - r * E_;
        Wsm[k * 132 + r] = W[(g0 + r) * E_ + k];
    }
    __syncthreads();

    int gg = threadIdx.x & 31;
    int tg = threadIdx.x >> 5;
    float acc[4][4];
#pragma unroll
    for (int i = 0; i < 4; i++)
#pragma unroll
        for (int j = 0; j < 4; j++) acc[i][j] = 0.f;

    const float* wp = &Wsm[gg * 4];
    const float* xp = &Xsm[tg * 4];
    for (int k = 0; k < E_; k++) {
        float4 w = *(const float4*)(wp + k * 132);
        float4 x = *(const float4*)(xp + k * 36);
        acc[0][0] += w.x * x.x; acc[0][1] += w.x * x.y; acc[0][2] += w.x * x.z; acc[0][3] += w.x * x.w;
        acc[1][0] += w.y * x.x; acc[1][1] += w.y * x.y; acc[1][2] += w.y * x.z; acc[1][3] += w.y * x.w;
        acc[2][0] += w.z * x.x; acc[2][1] += w.z * x.y; acc[2][2] += w.z * x.z; acc[2][3] += w.z * x.w;
        acc[3][0] += w.w * x.x; acc[3][1] += w.w * x.y; acc[3][2] += w.w * x.z; acc[3][3] += w.w * x.w;
    }

    float b0v = bias[g0 + gg * 4 + 0];
    float b1v = bias[g0 + gg * 4 + 1];
    float b2v = bias[g0 + gg * 4 + 2];
    float b3v = bias[g0 + gg * 4 + 3];
#pragma unroll
    for (int ti = 0; ti < 4; ti++) {
        int v = tt * 32 + tg * 4 + ti;
        if (v < V_) {
            float4 o = make_float4(acc[0][ti] + b0v, acc[1][ti] + b1v,
                                   acc[2][ti] + b2v, acc[3][ti] + b3v);
            *(float4*)&g_tab[dir][v * G_ + g0 + gg * 4] = o;
        }
    }
}

// ---------------- Kernel B: fused-direction HMMA LSTM --------------------
// 64 CTAs x 512 threads: warps 0-7 = forward tile, warps 8-15 = backward
// tile of the SAME (btile, utile). Two independent flag-synchronized
// recurrences co-resident on one SM: one half's HMMA stream fills the
// other half's flag-wait/L2 bubbles. Per-half machinery identical to R15
// (PASSED, rel_err 1.1e-7); __syncthreads -> per-half named barriers.
// SMEM per half: Bsm 2x[32][264]fp16 (33792B) + Gex [2][4][16][34]f32
// (17408B) = 51200B; total 102400.
__global__ void __launch_bounds__(512, 1)
lstm_kernel(const float* __restrict__ Whhf, const float* __restrict__ Whhb,
            const int* __restrict__ data) {
    extern __shared__ char sp0[];
    int tida = threadIdx.x;
    int half = tida >> 8;            // 0 = fwd, 1 = bwd
    int tid  = tida & 255;
    char* sp = sp0 + half * 51200;
    uint32_t sbase = smem_u32(sp0) + (uint32_t)(half * 51200);
    const int off_G = 33792;
    float* Gex = (float*)(sp + off_G);   // [kh 2][gate 4][u 16][b 34]

    int dir   = half;
    int cid   = blockIdx.x;          // 0..63
    int btile = cid & 3;
    int utile = cid >> 2;
    int b0 = btile * 32, u0 = utile * 16;
    const float* Whh = dir ? Whhb : Whhf;

    int w = tid >> 5, lane = tid & 31;
    int mt = w & 3;     // gate (m-tile)
    int kh = w >> 2;    // k-half (0..1), 128 k each

    // ldmatrix lane addresses (pitch 528B = 264 halfs)
    uint32_t a_lane = sbase + (uint32_t)((mt * 16 + (lane & 15)) * 528 + (lane >> 4) * 16);
    uint32_t b_lane = sbase + (uint32_t)(((((lane >> 4) & 1) * 8 + (lane & 7)) * 528) + ((lane >> 3) & 1) * 16);
    uint32_t khoff = (uint32_t)(kh * 256);

    uint32_t af0[8][4], af1[8][4];

    // ---- one-time A fragment load: two fp16 planes (per half) ----
    {
        __half* Asm = (__half*)sp;
#pragma unroll 1
        for (int p = 0; p < 2; p++) {
            for (int idx = tid; idx < 64 * 256; idx += 256) {
                int r = idx >> 8, k = idx & 255;
                int gate = r >> 4, ul = r & 15;
                float wv = Whh[(gate * 256 + u0 + ul) * 256 + k];
                __half o;
                if (p == 0) o = __float2half(wv);
                else {
                    float w0 = __half2float(__float2half(wv));
                    o = __float2half(wv - w0);
                }
                Asm[r * 264 + k] = o;
            }
            HALF_BAR(half);
            if (p == 0) {
#pragma unroll
                for (int kt = 0; kt < 8; kt++) LDMX4(af0[kt], a_lane + khoff + kt * 32);
            } else {
#pragma unroll
                for (int kt = 0; kt < 8; kt++) LDMX4(af1[kt], a_lane + khoff + kt * 32);
            }
            HALF_BAR(half);
        }
    }

    // epilogue cell assignment: thread = (unit ut, batches b2, b2+1)
    int ut = tid >> 4;
    int b2 = (tid & 15) * 2;
    float cst[2] = {0.f, 0.f};
    const float* tab = g_tab[dir];

    for (int ts = 0; ts < S_; ts++) {
        int t = dir ? (S_ - 1 - ts) : ts;

        // prefetch xg from the vocab table (independent of flag-gated h)
        int tokA = data[(b0 + b2) * S_ + t];
        int tokB = data[(b0 + b2 + 1) * S_ + t];
        float xv[2][4];
        {
            const float* xa = &tab[tokA * G_ + u0 + ut];
            const float* xb = &tab[tokB * G_ + u0 + ut];
#pragma unroll
            for (int g = 0; g < 4; g++) { xv[0][g] = xa[g * 256]; xv[1][g] = xb[g * 256]; }
        }

        if (ts > 0) {
            // wait for the 16 CTAs of this (dir,btile) group: step ts-1 done
            if (tid < 16) {
                volatile unsigned* fr = &g_flagx[dir][btile][tid][0];
                unsigned v;
                do { v = *fr; } while (!__all_sync(0xFFFFu, v >= (unsigned)ts));
                __threadfence();
            }
            HALF_BAR(half);

            // stage B = h(prev) 2 planes [32 b][256 k] -> pitch 264 fp16
            int tp = dir ? (t + 1) : (t - 1);
            const __half* hbase = &g_h2[dir][tp][0][b0][0];
#pragma unroll
            for (int it = 0; it < 8; it++) {
                int idx = tid + it * 256;       // 0..2047 uint4 moves
                int r = idx >> 5, q = idx & 31; // r: plane*32+batch, q: 8-half chunk
                int p = r >> 5, bI = r & 31;
                uint4 v = *(const uint4*)(hbase + p * (B_ * H_) + bI * H_ + q * 8);
                *(uint4*)(sp + p * 16896 + bI * 528 + q * 16) = v;
            }
            HALF_BAR(half);

            float dacc[4][4];
#pragma unroll
            for (int j = 0; j < 4; j++)
#pragma unroll
                for (int q = 0; q < 4; q++) dacc[j][q] = 0.f;

#pragma unroll
            for (int kt = 0; kt < 8; kt++) {
                uint32_t kb = khoff + kt * 32;
                uint32_t q0[8], q1[8];
                LDMX4(q0,     b_lane + kb);
                LDMX4(q0 + 4, b_lane + 8448 + kb);
                LDMX4(q1,     b_lane + 16896 + kb);
                LDMX4(q1 + 4, b_lane + 16896 + 8448 + kb);
#pragma unroll
                for (int j = 0; j < 4; j++) {
                    const uint32_t* b0p = q0 + (j >> 1) * 4 + (j & 1) * 2;
                    const uint32_t* b1p = q1 + (j >> 1) * 4 + (j & 1) * 2;
                    mma16816h(dacc[j], af0[kt], b0p);   // a0 b0
                    mma16816h(dacc[j], af1[kt], b0p);   // a1 b0
                    mma16816h(dacc[j], af0[kt], b1p);   // a0 b1
                }
            }

            // Gex partial-sum exchange: [kh][gate][unit][batch]
            {
                float* gbase = &Gex[kh * 2176 + mt * 544];
                int r0 = lane >> 2;
                int c0 = (lane & 3) * 2;
#pragma unroll
                for (int j = 0; j < 4; j++) {
                    int cb = j * 8 + c0;
                    *(float2*)&gbase[r0 * 34 + cb]       = make_float2(dacc[j][0], dacc[j][1]);
                    *(float2*)&gbase[(r0 + 8) * 34 + cb] = make_float2(dacc[j][2], dacc[j][3]);
                }
            }
            HALF_BAR(half);
        }

        // ---- epilogue: 2 cells per thread ----
#pragma unroll
        for (int c = 0; c < 2; c++) {
            float ai = xv[c][0], af = xv[c][1], ag = xv[c][2], ao = xv[c][3];
            if (ts > 0) {
                int gi = ut * 34 + b2 + c;
                ai += Gex[0 * 544 + gi] + Gex[2176 + 0 * 544 + gi];
                af += Gex[1 * 544 + gi] + Gex[2176 + 1 * 544 + gi];
                ag += Gex[2 * 544 + gi] + Gex[2176 + 2 * 544 + gi];
                ao += Gex[3 * 544 + gi] + Gex[2176 + 3 * 544 + gi];
            }
            cst[c] = fsig(af) * cst[c] + fsig(ai) * ftanh(ag);
            float h = fsig(ao) * ftanh(cst[c]);
            __half h0 = __float2half(h);
            __half h1 = __float2half(h - __half2float(h0));
            __half* hd = &g_h2[dir][t][0][b0 + b2 + c][u0 + ut];
            hd[0]       = h0;
            hd[B_ * H_] = h1;
            // fp32 transposed copy for MLP
            g_hT[dir][(t * H_ + u0 + ut) * B_ + b0 + b2 + c] = h;
        }

        // release: h visible, then publish flag (per-half)
        __threadfence();
        HALF_BAR(half);
        if (tid == 0)
            *(volatile unsigned*)&g_flagx[dir][btile][utile][0] = (unsigned)(ts + 1);
    }
}

// ---------------- Kernel C: MLP emissions (fp32 transposed h) ------------
__global__ void mlp_kernel(const float* __restrict__ mlpW,
                           const float* __restrict__ mlpb) {
    __shared__ float Wsm[T_ * 2 * H_];
    for (int i = threadIdx.x; i < T_ * 2 * H_; i += 128) Wsm[i] = mlpW[i];
    __syncthreads();

    int s = blockIdx.x;
    int b = threadIdx.x;

    float acc[T_];
#pragma unroll
    for (int t = 0; t < T_; t++) acc[t] = 0.f;

    const float* hf = &g_hT[0][(s * H_) * B_ + b];
    const float* hb = &g_hT[1][(s * H_) * B_ + b];
#pragma unroll 4
    for (int k = 0; k < H_; k++) {
        float v1 = hf[k * B_];
        float v2 = hb[k * B_];
#pragma unroll
        for (int t = 0; t < T_; t++) {
            acc[t] += v1 * Wsm[t * 512 + k];
            acc[t] += v2 * Wsm[t * 512 + 256 + k];
        }
    }
#pragma unroll
    for (int t = 0; t < T_; t++)
        g_em[(b * S_ + s) * T_ + t] = acc[t] + mlpb[t];
}

// ---------------- Kernel D: CRF Viterbi (one warp per batch) -------------
__global__ void viterbi_kernel(const int* __restrict__ data,
                               const float* __restrict__ stt,
                               const float* __restrict__ trn,
                               const float* __restrict__ ett,
                               float* __restrict__ out) {
    __shared__ int sbp[2][S_][10];
    int w = threadIdx.x >> 5, lane = threadIdx.x & 31;
    int b = blockIdx.x * 2 + w;
    int cc = lane < T_ ? lane : (T_ - 1);

    int cnt = 0;
    for (int s = lane; s < S_; s += 32) cnt += (data[b * S_ + s] != 0);
    for (int off = 16; off; off >>= 1) cnt += __shfl_xor_sync(0xFFFFFFFFu, cnt, off);
    int len = cnt;

    float tr[T_];
#pragma unroll
    for (int p = 0; p < T_; p++) tr[p] = trn[p * T_ + cc];

    float score = stt[cc] + g_em[(b * S_ + 0) * T_ + cc];
    float e_next = g_em[(b * S_ + 1) * T_ + cc];

    for (int t = 1; t < S_; t++) {
        float e = e_next;
        if (t + 1 < S_) e_next = g_em[(b * S_ + t + 1) * T_ + cc];
        float best = -1e30f; int bp = 0;
#pragma unroll
        for (int p = 0; p < T_; p++) {
            float sp = __shfl_sync(0xFFFFFFFFu, score, p);
            float cand = sp + tr[p] + e;
            if (cand > best) { best = cand; bp = p; }   // first-max tie-break
        }
        if (lane < T_) sbp[w][t][lane] = bp;
        if (t < len) score = best;
    }

    float fin = score + ett[cc];
    float bestf = -1e30f; int tag = 0;
#pragma unroll
    for (int p = 0; p < T_; p++) {
        float v = __shfl_sync(0xFFFFFFFFu, fin, p);
        if (v > bestf) { bestf = v; tag = p; }
    }
    if (lane == 0) out[B_ * S_ + b] = bestf;

    if (lane == 0) out[b * S_ + (S_ - 1)] = ((S_ - 1) < len) ? (float)tag : 0.f;
    for (int s2 = S_ - 2; s2 >= 0; s2--) {
        int bpv = sbp[w][s2 + 1][cc];
        int prev = __shfl_sync(0xFFFFFFFFu, bpv, tag);
        if (s2 + 1 < len) tag = prev;
        if (lane == 0) out[b * S_ + s2] = (s2 < len) ? (float)tag : 0.f;
    }
}

// ---------------- launch ----------------
extern "C" void kernel_launch(void* const* d_in, const int* in_sizes, int n_in,
                              void* d_out, int out_size) {
    const int*   data = (const int*)d_in[0];
    // d_in[1] = mask (ignored; mask == (data != 0))
    const float* emb  = (const float*)d_in[2];
    const float* Wihf = (const float*)d_in[3];
    const float* Whhf = (const float*)d_in[4];
    const float* bf   = (const float*)d_in[5];
    const float* Wihb = (const float*)d_in[6];
    const float* Whhb = (const float*)d_in[7];
    const float* bb   = (const float*)d_in[8];
    const float* mlpW = (const float*)d_in[9];
    const float* mlpb = (const float*)d_in[10];
    const float* stt  = (const float*)d_in[11];
    const float* trn  = (const float*)d_in[12];
    const float* ett  = (const float*)d_in[13];
    float* out = (float*)d_out;

    cudaFuncSetAttribute(vocab_kernel, cudaFuncAttributeMaxDynamicSharedMemorySize, 67200);
    cudaFuncSetAttribute(lstm_kernel,  cudaFuncAttributeMaxDynamicSharedMemorySize, 102400);

    reset_kernel<<<8, 512>>>();                                   // #1
    dim3 gV(188, 8);
    vocab_kernel<<<gV, 256, 67200>>>(emb, Wihf, bf, 0);           // #2
    vocab_kernel<<<gV, 256, 67200>>>(emb, Wihb, bb, 1);           // #3
    lstm_kernel<<<64, 512, 102400>>>(Whhf, Whhb, data);           // #4 (ncu slot)
    mlp_kernel<<<512, 128>>>(mlpW, mlpb);                         // #5
    viterbi_kernel<<<64, 64>>>(data, stt, trn, ett, out);         // #6
}

// round 17
// speedup vs baseline: 1.5202x; 1.5202x over previous
#include <cuda_runtime.h>
#include <cuda_bf16.h>
#include <cuda_fp16.h>
#include <cstdint>

// Problem dims
#define S_ 512
#define B_ 128
#define E_ 100
#define H_ 256
#define T_ 9
#define G_ 1024   // 4*H
#define V_ 6000
#define VPAD 6016

// ---------------- scratch (device globals; no allocations) ----------------
__device__ float g_tab[2][VPAD * G_];            // vocab projection table (+bias)
__device__ __half g_h2[2][S_][2][B_][H_];        // h 2-plane fp16 split (MMA B operand)
__device__ float g_hT[2][S_ * H_ * B_];          // fp32 h transposed [s][u][b] (for MLP)
__device__ float g_em[B_ * S_ * T_];             // emissions [b][s][t]
__device__ unsigned g_flagx[2][4][16][32];       // flags [dir][btile][utile], own 128B line

__device__ __forceinline__ float fsig(float x) {
    return __fdividef(1.f, 1.f + __expf(-x));
}
__device__ __forceinline__ float ftanh(float x) {
    return __fdividef(2.f, 1.f + __expf(-2.f * x)) - 1.f;
}

__device__ __forceinline__ uint32_t smem_u32(const void* p) {
    uint32_t a;
    asm("{ .reg .u64 t; cvta.to.shared.u64 t, %1; cvt.u32.u64 %0, t; }"
        : "=r"(a) : "l"(p));
    return a;
}

// acquire/release flag ops (replace threadfence + volatile)
__device__ __forceinline__ unsigned ld_acq(const unsigned* p) {
    unsigned v;
    asm volatile("ld.acquire.gpu.global.u32 %0, [%1];" : "=r"(v) : "l"(p) : "memory");
    return v;
}
__device__ __forceinline__ void st_rel(unsigned* p, unsigned v) {
    asm volatile("st.release.gpu.global.u32 [%0], %1;" :: "l"(p), "r"(v) : "memory");
}

#define LDMX4(r, addr) \
    asm volatile("ldmatrix.sync.aligned.m8n8.x4.shared.b16 {%0,%1,%2,%3}, [%4];" \
        : "=r"((r)[0]), "=r"((r)[1]), "=r"((r)[2]), "=r"((r)[3]) : "r"(addr))

__device__ __forceinline__ void mma16816h(float* d, const uint32_t* a, const uint32_t* b) {
    asm volatile(
        "mma.sync.aligned.m16n8k16.row.col.f32.f16.f16.f32 "
        "{%0,%1,%2,%3}, {%4,%5,%6,%7}, {%8,%9}, {%0,%1,%2,%3};"
        : "+f"(d[0]), "+f"(d[1]), "+f"(d[2]), "+f"(d[3])
        : "r"(a[0]), "r"(a[1]), "r"(a[2]), "r"(a[3]), "r"(b[0]), "r"(b[1]));
}

__global__ void reset_kernel() {
    int i = blockIdx.x * blockDim.x + threadIdx.x;
    if (i < 2 * 4 * 16 * 32) ((unsigned*)g_flagx)[i] = 0u;
}

// ---------------- Kernel A: VOCAB projection (per-direction launch) ------
__global__ void vocab_kernel(const float* __restrict__ emb,
                             const float* __restrict__ W,
                             const float* __restrict__ bias,
                             int dir) {
    extern __shared__ float sm[];
    float* Xsm = sm;          // [100][36]
    float* Wsm = sm + 3600;   // [100][132]

    int tt = blockIdx.x;
    int g0 = blockIdx.y * 128;

    for (int idx = threadIdx.x; idx < 32 * E_; idx += 256) {
        int j = idx / E_, k = idx - j * E_;
        int v = tt * 32 + j;
        int row = (v < V_) ? v : 0;
        Xsm[k * 36 + j] = emb[row * E_ + k];
    }
    for (int idx = threadIdx.x; idx < 128 * E_; idx += 256) {
        int r = idx / E_, k = idx - r * E_;
        Wsm[k * 132 + r] = W[(g0 + r) * E_ + k];
    }
    __syncthreads();

    int gg = threadIdx.x & 31;
    int tg = threadIdx.x >> 5;
    float acc[4][4];
#pragma unroll
    for (int i = 0; i < 4; i++)
#pragma unroll
        for (int j = 0; j < 4; j++) acc[i][j] = 0.f;

    const float* wp = &Wsm[gg * 4];
    const float* xp = &Xsm[tg * 4];
    for (int k = 0; k < E_; k++) {
        float4 w = *(const float4*)(wp + k * 132);
        float4 x = *(const float4*)(xp + k * 36);
        acc[0][0] += w.x * x.x; acc[0][1] += w.x * x.y; acc[0][2] += w.x * x.z; acc[0][3] += w.x * x.w;
        acc[1][0] += w.y * x.x; acc[1][1] += w.y * x.y; acc[1][2] += w.y * x.z; acc[1][3] += w.y * x.w;
        acc[2][0] += w.z * x.x; acc[2][1] += w.z * x.y; acc[2][2] += w.z * x.z; acc[2][3] += w.z * x.w;
        acc[3][0] += w.w * x.x; acc[3][1] += w.w * x.y; acc[3][2] += w.w * x.z; acc[3][3] += w.w * x.w;
    }

    float b0v = bias[g0 + gg * 4 + 0];
    float b1v = bias[g0 + gg * 4 + 1];
    float b2v = bias[g0 + gg * 4 + 2];
    float b3v = bias[g0 + gg * 4 + 3];
#pragma unroll
    for (int ti = 0; ti < 4; ti++) {
        int v = tt * 32 + tg * 4 + ti;
        if (v < V_) {
            float4 o = make_float4(acc[0][ti] + b0v, acc[1][ti] + b1v,
                                   acc[2][ti] + b2v, acc[3][ti] + b3v);
            *(float4*)&g_tab[dir][v * G_ + g0 + gg * 4] = o;
        }
    }
}

// ---------------- Kernel B: HMMA LSTM, 2-plane fp16 split (R15 base) -----
// 128 CTAs x 256 thr, __launch_bounds__(256,2). Changes vs R15:
//  - flag publish via st.release.gpu (no threadfence)
//  - flag poll via ld.acquire.gpu (no trailing threadfence)
//  - fp32 g_hT store moved AFTER the publish (off the critical path)
__global__ void __launch_bounds__(256, 2)
lstm_kernel(const float* __restrict__ Whhf, const float* __restrict__ Whhb,
            const int* __restrict__ data) {
    extern __shared__ char sp[];
    uint32_t sbase = smem_u32(sp);
    const int off_G = 33792;
    float* Gex = (float*)(sp + off_G);   // [kh 2][gate 4][u 16][b 34]

    int bx    = blockIdx.x;
    int dir   = bx >> 6;
    int cid   = bx & 63;
    int btile = cid & 3;
    int utile = cid >> 2;
    int b0 = btile * 32, u0 = utile * 16;
    const float* Whh = dir ? Whhb : Whhf;

    int tid = threadIdx.x, w = tid >> 5, lane = tid & 31;
    int mt = w & 3;     // gate (m-tile)
    int kh = w >> 2;    // k-half (0..1), 128 k each

    // ldmatrix lane addresses (pitch 528B = 264 halfs)
    uint32_t a_lane = sbase + (uint32_t)((mt * 16 + (lane & 15)) * 528 + (lane >> 4) * 16);
    uint32_t b_lane = sbase + (uint32_t)(((((lane >> 4) & 1) * 8 + (lane & 7)) * 528) + ((lane >> 3) & 1) * 16);
    uint32_t khoff = (uint32_t)(kh * 256);

    uint32_t af0[8][4], af1[8][4];

    // ---- one-time A fragment load: two fp16 planes ----
    {
        __half* Asm = (__half*)sp;
#pragma unroll 1
        for (int p = 0; p < 2; p++) {
            for (int idx = tid; idx < 64 * 256; idx += 256) {
                int r = idx >> 8, k = idx & 255;
                int gate = r >> 4, ul = r & 15;
                float wv = Whh[(gate * 256 + u0 + ul) * 256 + k];
                __half o;
                if (p == 0) o = __float2half(wv);
                else {
                    float w0 = __half2float(__float2half(wv));
                    o = __float2half(wv - w0);
                }
                Asm[r * 264 + k] = o;
            }
            __syncthreads();
            if (p == 0) {
#pragma unroll
                for (int kt = 0; kt < 8; kt++) LDMX4(af0[kt], a_lane + khoff + kt * 32);
            } else {
#pragma unroll
                for (int kt = 0; kt < 8; kt++) LDMX4(af1[kt], a_lane + khoff + kt * 32);
            }
            __syncthreads();
        }
    }

    // epilogue cell assignment: thread = (unit ut, batches b2, b2+1)
    int ut = tid >> 4;
    int b2 = (tid & 15) * 2;
    float cst[2] = {0.f, 0.f};
    const float* tab = g_tab[dir];

    for (int ts = 0; ts < S_; ts++) {
        int t = dir ? (S_ - 1 - ts) : ts;

        // prefetch xg from the vocab table (independent of flag-gated h)
        int tokA = data[(b0 + b2) * S_ + t];
        int tokB = data[(b0 + b2 + 1) * S_ + t];
        float xv[2][4];
        {
            const float* xa = &tab[tokA * G_ + u0 + ut];
            const float* xb = &tab[tokB * G_ + u0 + ut];
#pragma unroll
            for (int g = 0; g < 4; g++) { xv[0][g] = xa[g * 256]; xv[1][g] = xb[g * 256]; }
        }

        if (ts > 0) {
            // wait for the 16 CTAs of this (dir,btile) group: step ts-1 done
            if (tid < 16) {
                const unsigned* fr = &g_flagx[dir][btile][tid][0];
                unsigned v;
                do { v = ld_acq(fr); } while (!__all_sync(0xFFFFu, v >= (unsigned)ts));
            }
            __syncthreads();

            // stage B = h(prev) 2 planes [32 b][256 k] -> pitch 264 fp16
            int tp = dir ? (t + 1) : (t - 1);
            const __half* hbase = &g_h2[dir][tp][0][b0][0];
#pragma unroll
            for (int it = 0; it < 8; it++) {
                int idx = tid + it * 256;       // 0..2047 uint4 moves
                int r = idx >> 5, q = idx & 31; // r: plane*32+batch, q: 8-half chunk
                int p = r >> 5, bI = r & 31;
                uint4 v = *(const uint4*)(hbase + p * (B_ * H_) + bI * H_ + q * 8);
                *(uint4*)(sp + p * 16896 + bI * 528 + q * 16) = v;
            }
            __syncthreads();

            float dacc[4][4];
#pragma unroll
            for (int j = 0; j < 4; j++)
#pragma unroll
                for (int q = 0; q < 4; q++) dacc[j][q] = 0.f;

#pragma unroll
            for (int kt = 0; kt < 8; kt++) {
                uint32_t kb = khoff + kt * 32;
                uint32_t q0[8], q1[8];
                LDMX4(q0,     b_lane + kb);
                LDMX4(q0 + 4, b_lane + 8448 + kb);
                LDMX4(q1,     b_lane + 16896 + kb);
                LDMX4(q1 + 4, b_lane + 16896 + 8448 + kb);
#pragma unroll
                for (int j = 0; j < 4; j++) {
                    const uint32_t* b0p = q0 + (j >> 1) * 4 + (j & 1) * 2;
                    const uint32_t* b1p = q1 + (j >> 1) * 4 + (j & 1) * 2;
                    mma16816h(dacc[j], af0[kt], b0p);   // a0 b0
                    mma16816h(dacc[j], af1[kt], b0p);   // a1 b0
                    mma16816h(dacc[j], af0[kt], b1p);   // a0 b1
                }
            }

            // Gex partial-sum exchange: [kh][gate][unit][batch]
            {
                float* gbase = &Gex[kh * 2176 + mt * 544];
                int r0 = lane >> 2;
                int c0 = (lane & 3) * 2;
#pragma unroll
                for (int j = 0; j < 4; j++) {
                    int cb = j * 8 + c0;
                    *(float2*)&gbase[r0 * 34 + cb]       = make_float2(dacc[j][0], dacc[j][1]);
                    *(float2*)&gbase[(r0 + 8) * 34 + cb] = make_float2(dacc[j][2], dacc[j][3]);
                }
            }
            __syncthreads();
        }

        // ---- epilogue: 2 cells per thread ----
        float hsave[2];
#pragma unroll
        for (int c = 0; c < 2; c++) {
            float ai = xv[c][0], af = xv[c][1], ag = xv[c][2], ao = xv[c][3];
            if (ts > 0) {
                int gi = ut * 34 + b2 + c;
                ai += Gex[0 * 544 + gi] + Gex[2176 + 0 * 544 + gi];
                af += Gex[1 * 544 + gi] + Gex[2176 + 1 * 544 + gi];
                ag += Gex[2 * 544 + gi] + Gex[2176 + 2 * 544 + gi];
                ao += Gex[3 * 544 + gi] + Gex[2176 + 3 * 544 + gi];
            }
            cst[c] = fsig(af) * cst[c] + fsig(ai) * ftanh(ag);
            float h = fsig(ao) * ftanh(cst[c]);
            hsave[c] = h;
            __half h0 = __float2half(h);
            __half h1 = __float2half(h - __half2float(h0));
            __half* hd = &g_h2[dir][t][0][b0 + b2 + c][u0 + ut];
            hd[0]       = h0;
            hd[B_ * H_] = h1;
        }

        // release: barrier (all g_h2 stores issued), release-publish flag
        __syncthreads();
        if (tid == 0)
            st_rel(&g_flagx[dir][btile][utile][0], (unsigned)(ts + 1));

        // fp32 transposed copy for MLP — off the critical path
#pragma unroll
        for (int c = 0; c < 2; c++)
            g_hT[dir][(t * H_ + u0 + ut) * B_ + b0 + b2 + c] = hsave[c];
    }
}

// ---------------- Kernel C: MLP emissions (fp32 transposed h) ------------
__global__ void mlp_kernel(const float* __restrict__ mlpW,
                           const float* __restrict__ mlpb) {
    __shared__ float Wsm[T_ * 2 * H_];
    for (int i = threadIdx.x; i < T_ * 2 * H_; i += 128) Wsm[i] = mlpW[i];
    __syncthreads();

    int s = blockIdx.x;
    int b = threadIdx.x;

    float acc[T_];
#pragma unroll
    for (int t = 0; t < T_; t++) acc[t] = 0.f;

    const float* hf = &g_hT[0][(s * H_) * B_ + b];
    const float* hb = &g_hT[1][(s * H_) * B_ + b];
#pragma unroll 4
    for (int k = 0; k < H_; k++) {
        float v1 = hf[k * B_];
        float v2 = hb[k * B_];
#pragma unroll
        for (int t = 0; t < T_; t++) {
            acc[t] += v1 * Wsm[t * 512 + k];
            acc[t] += v2 * Wsm[t * 512 + 256 + k];
        }
    }
#pragma unroll
    for (int t = 0; t < T_; t++)
        g_em[(b * S_ + s) * T_ + t] = acc[t] + mlpb[t];
}

// ---------------- Kernel D: CRF Viterbi (one warp per batch) -------------
__global__ void viterbi_kernel(const int* __restrict__ data,
                               const float* __restrict__ stt,
                               const float* __restrict__ trn,
                               const float* __restrict__ ett,
                               float* __restrict__ out) {
    __shared__ int sbp[2][S_][10];
    int w = threadIdx.x >> 5, lane = threadIdx.x & 31;
    int b = blockIdx.x * 2 + w;
    int cc = lane < T_ ? lane : (T_ - 1);

    int cnt = 0;
    for (int s = lane; s < S_; s += 32) cnt += (data[b * S_ + s] != 0);
    for (int off = 16; off; off >>= 1) cnt += __shfl_xor_sync(0xFFFFFFFFu, cnt, off);
    int len = cnt;

    float tr[T_];
#pragma unroll
    for (int p = 0; p < T_; p++) tr[p] = trn[p * T_ + cc];

    float score = stt[cc] + g_em[(b * S_ + 0) * T_ + cc];
    float e_next = g_em[(b * S_ + 1) * T_ + cc];

    for (int t = 1; t < S_; t++) {
        float e = e_next;
        if (t + 1 < S_) e_next = g_em[(b * S_ + t + 1) * T_ + cc];
        float best = -1e30f; int bp = 0;
#pragma unroll
        for (int p = 0; p < T_; p++) {
            float sp = __shfl_sync(0xFFFFFFFFu, score, p);
            float cand = sp + tr[p] + e;
            if (cand > best) { best = cand; bp = p; }   // first-max tie-break
        }
        if (lane < T_) sbp[w][t][lane] = bp;
        if (t < len) score = best;
    }

    float fin = score + ett[cc];
    float bestf = -1e30f; int tag = 0;
#pragma unroll
    for (int p = 0; p < T_; p++) {
        float v = __shfl_sync(0xFFFFFFFFu, fin, p);
        if (v > bestf) { bestf = v; tag = p; }
    }
    if (lane == 0) out[B_ * S_ + b] = bestf;

    if (lane == 0) out[b * S_ + (S_ - 1)] = ((S_ - 1) < len) ? (float)tag : 0.f;
    for (int s2 = S_ - 2; s2 >= 0; s2--) {
        int bpv = sbp[w][s2 + 1][cc];
        int prev = __shfl_sync(0xFFFFFFFFu, bpv, tag);
        if (s2 + 1 < len) tag = prev;
        if (lane == 0) out[b * S_ + s2] = (s2 < len) ? (float)tag : 0.f;
    }
}

// ---------------- launch ----------------
extern "C" void kernel_launch(void* const* d_in, const int* in_sizes, int n_in,
                              void* d_out, int out_size) {
    const int*   data = (const int*)d_in[0];
    // d_in[1] = mask (ignored; mask == (data != 0))
    const float* emb  = (const float*)d_in[2];
    const float* Wihf = (const float*)d_in[3];
    const float* Whhf = (const float*)d_in[4];
    const float* bf   = (const float*)d_in[5];
    const float* Wihb = (const float*)d_in[6];
    const float* Whhb = (const float*)d_in[7];
    const float* bb   = (const float*)d_in[8];
    const float* mlpW = (const float*)d_in[9];
    const float* mlpb = (const float*)d_in[10];
    const float* stt  = (const float*)d_in[11];
    const float* trn  = (const float*)d_in[12];
    const float* ett  = (const float*)d_in[13];
    float* out = (float*)d_out;

    cudaFuncSetAttribute(vocab_kernel, cudaFuncAttributeMaxDynamicSharedMemorySize, 67200);
    cudaFuncSetAttribute(lstm_kernel,  cudaFuncAttributeMaxDynamicSharedMemorySize, 51200);

    reset_kernel<<<8, 512>>>();                                   // #1
    dim3 gV(188, 8);
    vocab_kernel<<<gV, 256, 67200>>>(emb, Wihf, bf, 0);           // #2
    vocab_kernel<<<gV, 256, 67200>>>(emb, Wihb, bb, 1);           // #3
    lstm_kernel<<<128, 256, 51200>>>(Whhf, Whhb, data);           // #4 (ncu slot)
    mlp_kernel<<<512, 128>>>(mlpW, mlpb);                         // #5
    viterbi_kernel<<<64, 64>>>(data, stt, trn, ett, out);         // #6
}